// round 1
// baseline (speedup 1.0000x reference)
#include <cuda_runtime.h>
#include <math.h>

// Problem: NNclrInfoNCECriterion
//   embedding [4096,256] f32, preds [4096,256] f32, queue [65536,256] f32 (rows unit-norm)
//   idx = argmax_q(embedding @ queue^T)  (fp32-exact argmax, first-index ties)
//   nearest = queue[idx]; logits_ab = nn_a @ preds_b^T /0.1 ; logits_ba = nn_b @ preds_a^T /0.1
//   loss = CE(logits_ab, arange)/2 + CE(logits_ba, arange)/2    (scalar f32)

#define B_TOT 4096
#define HALF  2048
#define DDIM  256
#define QTOT  65536
#define QS    32            // queue splits for argmax partials
#define QCHUNK (QTOT/QS)    // 2048
#define BM 128
#define BN 128
#define BK 32
#define LDA 132             // padded smem leading dim (floats)
#define CS 4                // column splits in logits kernel
#define NCOL (HALF/CS)      // 512
#define INV_T 10.0f

// ---- scratch (no allocations allowed -> device globals) ----
__device__ float g_pmax[B_TOT * QS];
__device__ int   g_pidx[B_TOT * QS];
__device__ int   g_gidx[B_TOT];
__device__ float g_lsem[2 * HALF * CS];
__device__ float g_lses[2 * HALF * CS];
__device__ float g_rowloss[2 * HALF];

// ============================================================
// Kernel 1: fused GEMM + per-row argmax partials.
// CTA: 128 emb rows x 2048 queue rows (one q-split), K=256.
// A (emb tile, transposed As[k][m]) persistent in smem.
// B (queue) double-buffered in 32-k chunks.
// 256 threads, 8x8 microtile each (16x16 thread grid).
// ============================================================
__global__ __launch_bounds__(256, 1)
void argmax_partial_kernel(const float* __restrict__ emb,
                           const float* __restrict__ queue)
{
    extern __shared__ float smem[];
    float* As   = smem;                       // [256][LDA]
    float* Bs   = smem + 256 * LDA;           // [2][BK][LDA]
    float* redV = Bs + 2 * BK * LDA;          // [BM][16]
    int*   redI = (int*)(redV + BM * 16);     // [BM][16]

    const int tid = threadIdx.x;
    const int tx = tid & 15;
    const int ty = tid >> 4;
    const int embTile = blockIdx.x * BM;
    const int qBase   = blockIdx.y * QCHUNK;

    // Load A tile transposed: As[k][m] = emb[embTile+m][k].  tid == k (0..255).
    #pragma unroll 4
    for (int m = 0; m < BM; ++m)
        As[tid * LDA + m] = emb[(size_t)(embTile + m) * DDIM + tid];
    __syncthreads();

    const int bn  = tid >> 1;        // B row within tile (0..127)
    const int bks = (tid & 1) * 16;  // k offset within 32-chunk

    float best[8];
    int   bidx[8];
    #pragma unroll
    for (int r = 0; r < 8; ++r) { best[r] = -INFINITY; bidx[r] = 0; }

    for (int qt = 0; qt < QCHUNK / BN; ++qt) {
        float acc[8][8];
        #pragma unroll
        for (int r = 0; r < 8; ++r)
            #pragma unroll
            for (int c = 0; c < 8; ++c) acc[r][c] = 0.0f;

        // prologue: chunk 0 -> buffer 0
        {
            const float* src = queue + (size_t)(qBase + qt * BN + bn) * DDIM + bks;
            #pragma unroll
            for (int j = 0; j < 4; ++j) {
                float4 v = *(const float4*)(src + 4 * j);
                Bs[(bks + 4*j + 0) * LDA + bn] = v.x;
                Bs[(bks + 4*j + 1) * LDA + bn] = v.y;
                Bs[(bks + 4*j + 2) * LDA + bn] = v.z;
                Bs[(bks + 4*j + 3) * LDA + bn] = v.w;
            }
        }
        __syncthreads();

        for (int kb = 0; kb < DDIM / BK; ++kb) {
            float4 pre[4];
            const bool hasNext = (kb + 1) < (DDIM / BK);
            if (hasNext) {
                const float* src = queue + (size_t)(qBase + qt * BN + bn) * DDIM
                                 + (kb + 1) * BK + bks;
                #pragma unroll
                for (int j = 0; j < 4; ++j) pre[j] = *(const float4*)(src + 4 * j);
            }

            const float* a_base = As + (kb * BK) * LDA + ty * 8;
            const float* b_base = Bs + (kb & 1) * BK * LDA + tx * 8;
            #pragma unroll
            for (int kk = 0; kk < BK; ++kk) {
                float4 a0 = *(const float4*)(a_base + kk * LDA);
                float4 a1 = *(const float4*)(a_base + kk * LDA + 4);
                float4 b0 = *(const float4*)(b_base + kk * LDA);
                float4 b1 = *(const float4*)(b_base + kk * LDA + 4);
                float av[8] = {a0.x,a0.y,a0.z,a0.w,a1.x,a1.y,a1.z,a1.w};
                float bv[8] = {b0.x,b0.y,b0.z,b0.w,b1.x,b1.y,b1.z,b1.w};
                #pragma unroll
                for (int r = 0; r < 8; ++r)
                    #pragma unroll
                    for (int c = 0; c < 8; ++c)
                        acc[r][c] = fmaf(av[r], bv[c], acc[r][c]);
            }

            if (hasNext) {
                float* dst = Bs + ((kb + 1) & 1) * BK * LDA;
                #pragma unroll
                for (int j = 0; j < 4; ++j) {
                    dst[(bks + 4*j + 0) * LDA + bn] = pre[j].x;
                    dst[(bks + 4*j + 1) * LDA + bn] = pre[j].y;
                    dst[(bks + 4*j + 2) * LDA + bn] = pre[j].z;
                    dst[(bks + 4*j + 3) * LDA + bn] = pre[j].w;
                }
            }
            __syncthreads();
        }

        // argmax epilogue (ascending index order + strict > keeps first index)
        const int colBase = qBase + qt * BN + tx * 8;
        #pragma unroll
        for (int r = 0; r < 8; ++r)
            #pragma unroll
            for (int c = 0; c < 8; ++c) {
                float v = acc[r][c];
                if (v > best[r]) { best[r] = v; bidx[r] = colBase + c; }
            }
    }

    // merge across the 16 tx-threads sharing each row
    #pragma unroll
    for (int r = 0; r < 8; ++r) {
        redV[(ty * 8 + r) * 16 + tx] = best[r];
        redI[(ty * 8 + r) * 16 + tx] = bidx[r];
    }
    __syncthreads();
    if (tid < BM) {
        float bv = -INFINITY; int bi = 0x7fffffff;
        #pragma unroll
        for (int t = 0; t < 16; ++t) {
            float v = redV[tid * 16 + t];
            int   i = redI[tid * 16 + t];
            if (v > bv || (v == bv && i < bi)) { bv = v; bi = i; }
        }
        g_pmax[(size_t)(embTile + tid) * QS + blockIdx.y] = bv;
        g_pidx[(size_t)(embTile + tid) * QS + blockIdx.y] = bi;
    }
}

// ============================================================
// Kernel 2: reduce QS partials per row -> g_gidx
// ============================================================
__global__ void argmax_reduce_kernel()
{
    int r = blockIdx.x * blockDim.x + threadIdx.x;
    if (r < B_TOT) {
        float bv = -INFINITY; int bi = 0x7fffffff;
        #pragma unroll
        for (int s = 0; s < QS; ++s) {
            float v = g_pmax[(size_t)r * QS + s];
            int   i = g_pidx[(size_t)r * QS + s];
            if (v > bv || (v == bv && i < bi)) { bv = v; bi = i; }
        }
        g_gidx[r] = bi;
    }
}

// ============================================================
// Kernel 3: logits GEMM + online logsumexp partials.
// dir 0: nn_a @ preds_b^T ; dir 1: nn_b @ preds_a^T. Scale 1/T=10.
// A rows gathered from queue via g_gidx.
// ============================================================
__global__ __launch_bounds__(256, 1)
void logits_lse_kernel(const float* __restrict__ queue,
                       const float* __restrict__ preds)
{
    extern __shared__ float smem[];
    float* As   = smem;
    float* Bs   = smem + 256 * LDA;
    float* redM = Bs + 2 * BK * LDA;          // [BM][16]
    float* redS = redM + BM * 16;             // [BM][16]

    const int tid = threadIdx.x;
    const int tx = tid & 15;
    const int ty = tid >> 4;
    const int dir      = blockIdx.z;
    const int rowBase  = blockIdx.x * BM;
    const int colBase  = blockIdx.y * NCOL;
    const int predBase = (dir == 0) ? HALF : 0;
    const int idxBase  = dir * HALF;

    #pragma unroll 4
    for (int m = 0; m < BM; ++m) {
        int qi = g_gidx[idxBase + rowBase + m];
        As[tid * LDA + m] = queue[(size_t)qi * DDIM + tid];
    }
    __syncthreads();

    const int bn  = tid >> 1;
    const int bks = (tid & 1) * 16;

    float lm[8], ls[8];
    #pragma unroll
    for (int r = 0; r < 8; ++r) { lm[r] = -INFINITY; ls[r] = 0.0f; }

    for (int qt = 0; qt < NCOL / BN; ++qt) {
        float acc[8][8];
        #pragma unroll
        for (int r = 0; r < 8; ++r)
            #pragma unroll
            for (int c = 0; c < 8; ++c) acc[r][c] = 0.0f;

        {
            const float* src = preds + (size_t)(predBase + colBase + qt * BN + bn) * DDIM + bks;
            #pragma unroll
            for (int j = 0; j < 4; ++j) {
                float4 v = *(const float4*)(src + 4 * j);
                Bs[(bks + 4*j + 0) * LDA + bn] = v.x;
                Bs[(bks + 4*j + 1) * LDA + bn] = v.y;
                Bs[(bks + 4*j + 2) * LDA + bn] = v.z;
                Bs[(bks + 4*j + 3) * LDA + bn] = v.w;
            }
        }
        __syncthreads();

        for (int kb = 0; kb < DDIM / BK; ++kb) {
            float4 pre[4];
            const bool hasNext = (kb + 1) < (DDIM / BK);
            if (hasNext) {
                const float* src = preds + (size_t)(predBase + colBase + qt * BN + bn) * DDIM
                                 + (kb + 1) * BK + bks;
                #pragma unroll
                for (int j = 0; j < 4; ++j) pre[j] = *(const float4*)(src + 4 * j);
            }
            const float* a_base = As + (kb * BK) * LDA + ty * 8;
            const float* b_base = Bs + (kb & 1) * BK * LDA + tx * 8;
            #pragma unroll
            for (int kk = 0; kk < BK; ++kk) {
                float4 a0 = *(const float4*)(a_base + kk * LDA);
                float4 a1 = *(const float4*)(a_base + kk * LDA + 4);
                float4 b0 = *(const float4*)(b_base + kk * LDA);
                float4 b1 = *(const float4*)(b_base + kk * LDA + 4);
                float av[8] = {a0.x,a0.y,a0.z,a0.w,a1.x,a1.y,a1.z,a1.w};
                float bv[8] = {b0.x,b0.y,b0.z,b0.w,b1.x,b1.y,b1.z,b1.w};
                #pragma unroll
                for (int r = 0; r < 8; ++r)
                    #pragma unroll
                    for (int c = 0; c < 8; ++c)
                        acc[r][c] = fmaf(av[r], bv[c], acc[r][c]);
            }
            if (hasNext) {
                float* dst = Bs + ((kb + 1) & 1) * BK * LDA;
                #pragma unroll
                for (int j = 0; j < 4; ++j) {
                    dst[(bks + 4*j + 0) * LDA + bn] = pre[j].x;
                    dst[(bks + 4*j + 1) * LDA + bn] = pre[j].y;
                    dst[(bks + 4*j + 2) * LDA + bn] = pre[j].z;
                    dst[(bks + 4*j + 3) * LDA + bn] = pre[j].w;
                }
            }
            __syncthreads();
        }

        // online logsumexp over this tile's columns
        #pragma unroll
        for (int r = 0; r < 8; ++r)
            #pragma unroll
            for (int c = 0; c < 8; ++c) {
                float x = acc[r][c] * INV_T;
                if (x > lm[r]) {
                    ls[r] = ls[r] * expf(lm[r] - x) + 1.0f;
                    lm[r] = x;
                } else {
                    ls[r] += expf(x - lm[r]);
                }
            }
    }

    #pragma unroll
    for (int r = 0; r < 8; ++r) {
        redM[(ty * 8 + r) * 16 + tx] = lm[r];
        redS[(ty * 8 + r) * 16 + tx] = ls[r];
    }
    __syncthreads();
    if (tid < BM) {
        float M = -INFINITY;
        #pragma unroll
        for (int t = 0; t < 16; ++t) M = fmaxf(M, redM[tid * 16 + t]);
        float S = 0.0f;
        #pragma unroll
        for (int t = 0; t < 16; ++t) S += redS[tid * 16 + t] * expf(redM[tid * 16 + t] - M);
        int row = rowBase + tid;
        g_lsem[(size_t)(idxBase + row) * CS + blockIdx.y] = M;
        g_lses[(size_t)(idxBase + row) * CS + blockIdx.y] = S;
    }
}

// ============================================================
// Kernel 4: per-row loss = logsumexp - diagonal logit.
// One warp per 4 rows; diag dot computed directly.
// ============================================================
__global__ void ce_finalize_kernel(const float* __restrict__ queue,
                                   const float* __restrict__ preds)
{
    int warp = (blockIdx.x * blockDim.x + threadIdx.x) >> 5;
    int lane = threadIdx.x & 31;
    #pragma unroll
    for (int rr = 0; rr < 4; ++rr) {
        int ridx = warp * 4 + rr;            // 0..4095
        if (ridx >= 2 * HALF) return;
        int dir = ridx >> 11;
        int row = ridx & (HALF - 1);
        int qi  = g_gidx[dir * HALF + row];
        const float* a = queue + (size_t)qi * DDIM;
        const float* b = preds + (size_t)(((dir == 0) ? HALF : 0) + row) * DDIM;
        float p = 0.0f;
        for (int k = lane; k < DDIM; k += 32) p = fmaf(a[k], b[k], p);
        #pragma unroll
        for (int o = 16; o; o >>= 1) p += __shfl_xor_sync(0xffffffffu, p, o);
        if (lane == 0) {
            float M = -INFINITY;
            #pragma unroll
            for (int t = 0; t < CS; ++t) M = fmaxf(M, g_lsem[(size_t)ridx * CS + t]);
            float S = 0.0f;
            #pragma unroll
            for (int t = 0; t < CS; ++t)
                S += g_lses[(size_t)ridx * CS + t] * expf(g_lsem[(size_t)ridx * CS + t] - M);
            float lse = M + logf(S);
            g_rowloss[ridx] = lse - p * INV_T;
        }
    }
}

// ============================================================
// Kernel 5: deterministic final reduction -> scalar loss
// ============================================================
__global__ void final_sum_kernel(float* __restrict__ out)
{
    __shared__ float sm0[256], sm1[256];
    int tid = threadIdx.x;
    float s0 = 0.0f, s1 = 0.0f;
    for (int i = tid; i < HALF; i += 256) {
        s0 += g_rowloss[i];
        s1 += g_rowloss[HALF + i];
    }
    sm0[tid] = s0; sm1[tid] = s1;
    __syncthreads();
    for (int o = 128; o; o >>= 1) {
        if (tid < o) { sm0[tid] += sm0[tid + o]; sm1[tid] += sm1[tid + o]; }
        __syncthreads();
    }
    if (tid == 0)
        out[0] = 0.5f * (sm0[0] / (float)HALF + sm1[0] / (float)HALF);
}

// ============================================================
extern "C" void kernel_launch(void* const* d_in, const int* in_sizes, int n_in,
                              void* d_out, int out_size)
{
    const float* emb   = (const float*)d_in[0];
    const float* preds = (const float*)d_in[1];
    const float* queue = (const float*)d_in[2];
    float* out = (float*)d_out;

    const size_t smemBytes = (size_t)(256 * LDA + 2 * BK * LDA) * sizeof(float)
                           + (size_t)BM * 16 * (sizeof(float) + sizeof(int));
    cudaFuncSetAttribute(argmax_partial_kernel,
                         cudaFuncAttributeMaxDynamicSharedMemorySize, (int)smemBytes);
    cudaFuncSetAttribute(logits_lse_kernel,
                         cudaFuncAttributeMaxDynamicSharedMemorySize, (int)smemBytes);

    argmax_partial_kernel<<<dim3(B_TOT / BM, QS), 256, smemBytes>>>(emb, queue);
    argmax_reduce_kernel<<<B_TOT / 256, 256>>>();
    logits_lse_kernel<<<dim3(HALF / BM, CS, 2), 256, smemBytes>>>(queue, preds);
    ce_finalize_kernel<<<128, 256>>>(queue, preds);
    final_sum_kernel<<<1, 256>>>(out);
}

// round 5
// speedup vs baseline: 7.0977x; 7.0977x over previous
#include <cuda_runtime.h>
#include <cuda_bf16.h>
#include <math.h>
#include <stdint.h>

// NNclrInfoNCECriterion on GB300 (sm_103a via compute_103 PTX -> legacy mma.sync path).
// Stage 1: approx sim GEMM in bf16 (mma.sync m16n8k16) with per-row approx top-2
//          candidates, then exact fp32 rescore of candidates -> argmax indices.
// Stage 2: logits GEMM + logsumexp + CE in fp32 (known-correct from R1).

#define B_TOT 4096
#define HALF  2048
#define DDIM  256
#define QTOT  65536
#define QS    32
#define QCHUNK (QTOT/QS)     // 2048
#define NTILE  (QCHUNK/128)  // 16 col-tiles per CTA
#define CS 4
#define NCOL (HALF/CS)
#define BM 128
#define BK 32
#define LDA 132
#define INV_T 10.0f
#define RESCORE_MARGIN 0.02f

// ---------------- scratch globals ----------------
__device__ __nv_bfloat16 g_qhi[(size_t)QTOT * DDIM];
__device__ __nv_bfloat16 g_ehi[(size_t)B_TOT * DDIM];
__device__ float g_c2val[(size_t)B_TOT * 2 * QS];   // [row][ctaY][2]
__device__ int   g_c2idx[(size_t)B_TOT * 2 * QS];
__device__ int   g_gidx[B_TOT];
__device__ float g_lsem[2 * HALF * CS];
__device__ float g_lses[2 * HALF * CS];
__device__ float g_rowloss[2 * HALF];

// ---------------- helpers ----------------
__device__ __forceinline__ uint32_t smem_to_u32(const void* p) {
    uint32_t a;
    asm("{ .reg .u64 t; cvta.to.shared.u64 t, %1; cvt.u32.u64 %0, t; }" : "=r"(a) : "l"(p));
    return a;
}
__device__ __forceinline__ void cp_async16(uint32_t dst, const void* src) {
    asm volatile("cp.async.cg.shared.global [%0], [%1], 16;" :: "r"(dst), "l"(src) : "memory");
}
#define CP_COMMIT() asm volatile("cp.async.commit_group;" ::: "memory")
#define CP_WAIT0()  asm volatile("cp.async.wait_group 0;" ::: "memory")

__device__ __forceinline__ void ldsm_x4(uint32_t& r0, uint32_t& r1, uint32_t& r2, uint32_t& r3,
                                        uint32_t addr) {
    asm volatile("ldmatrix.sync.aligned.m8n8.x4.shared.b16 {%0,%1,%2,%3}, [%4];"
                 : "=r"(r0), "=r"(r1), "=r"(r2), "=r"(r3) : "r"(addr));
}
__device__ __forceinline__ void mma16816(float& d0, float& d1, float& d2, float& d3,
                                         uint32_t a0, uint32_t a1, uint32_t a2, uint32_t a3,
                                         uint32_t b0, uint32_t b1) {
    asm volatile("mma.sync.aligned.m16n8k16.row.col.f32.bf16.bf16.f32 "
                 "{%0,%1,%2,%3}, {%4,%5,%6,%7}, {%8,%9}, {%0,%1,%2,%3};"
                 : "+f"(d0), "+f"(d1), "+f"(d2), "+f"(d3)
                 : "r"(a0), "r"(a1), "r"(a2), "r"(a3), "r"(b0), "r"(b1));
}
// swizzled byte offset inside a [rows x 256 bf16] tile (512 B rows)
__device__ __forceinline__ uint32_t sw(uint32_t row, uint32_t kb) {
    return row * 512u + (kb ^ ((row & 7u) << 4));
}

// ============================================================
// fp32 -> bf16 conversion
// ============================================================
__global__ void to_bf16_kernel(const float* __restrict__ src,
                               __nv_bfloat16* __restrict__ dst, int n4)
{
    int i = blockIdx.x * blockDim.x + threadIdx.x;
    if (i < n4) {
        float4 v = ((const float4*)src)[i];
        ((__nv_bfloat162*)dst)[2 * i]     = __floats2bfloat162_rn(v.x, v.y);
        ((__nv_bfloat162*)dst)[2 * i + 1] = __floats2bfloat162_rn(v.z, v.w);
    }
}

// ============================================================
// Kernel 1: bf16 mma.sync sim GEMM + per-row approx top-2 candidates.
// grid (32 row-tiles, 32 col-groups), 512 threads (16 warps, 4x4 warp grid).
// CTA tile M=128 x N=128, K=256. A smem-resident; B double-buffered cp.async.
// ============================================================
__global__ __launch_bounds__(512, 1)
void argmax_mma_kernel()
{
    extern __shared__ char smem[];
    const uint32_t sb   = smem_to_u32(smem);
    const uint32_t as32 = (sb + 1023u) & ~1023u;   // A tile: 64KB
    const uint32_t bs32 = as32 + 65536u;           // B tiles: 2 x 64KB

    const int tid  = threadIdx.x;
    const int lane = tid & 31;
    const int w    = tid >> 5;
    const int wm   = w >> 2;          // 0..3  (32-row slab)
    const int wn   = w & 3;           // 0..3  (32-col slab)
    const int rowBase = blockIdx.x * 128;
    const int qBase   = blockIdx.y * QCHUNK;

    // ---- async load A (128x256 bf16) + B tile 0 ----
    #pragma unroll
    for (int i = 0; i < 8; ++i) {
        int c = i * 512 + tid;
        uint32_t row = (uint32_t)(c >> 5), k16 = (uint32_t)(c & 31);
        cp_async16(as32 + sw(row, k16 * 16),
                   (const char*)(g_ehi + (size_t)(rowBase + row) * DDIM) + k16 * 16);
    }
    #pragma unroll
    for (int i = 0; i < 8; ++i) {
        int c = i * 512 + tid;
        uint32_t row = (uint32_t)(c >> 5), k16 = (uint32_t)(c & 31);
        cp_async16(bs32 + sw(row, k16 * 16),
                   (const char*)(g_qhi + (size_t)(qBase + row) * DDIM) + k16 * 16);
    }
    CP_COMMIT();
    CP_WAIT0();
    __syncthreads();

    float tv[4][2];
    int   tix[4][2];
    #pragma unroll
    for (int s = 0; s < 4; ++s) {
        tv[s][0] = -INFINITY; tv[s][1] = -INFINITY;
        tix[s][0] = 0x7fffffff; tix[s][1] = 0x7fffffff;
    }

    for (int ct = 0; ct < NTILE; ++ct) {
        // prefetch next B tile
        if (ct + 1 < NTILE) {
            const uint32_t nbuf = bs32 + (uint32_t)((ct + 1) & 1) * 65536u;
            #pragma unroll
            for (int i = 0; i < 8; ++i) {
                int c = i * 512 + tid;
                uint32_t row = (uint32_t)(c >> 5), k16 = (uint32_t)(c & 31);
                cp_async16(nbuf + sw(row, k16 * 16),
                           (const char*)(g_qhi + (size_t)(qBase + (ct + 1) * 128 + row) * DDIM) + k16 * 16);
            }
            CP_COMMIT();
        }

        const uint32_t bbuf = bs32 + (uint32_t)(ct & 1) * 65536u;
        float acc[2][4][4];
        #pragma unroll
        for (int mi = 0; mi < 2; ++mi)
            #pragma unroll
            for (int ni = 0; ni < 4; ++ni)
                #pragma unroll
                for (int d = 0; d < 4; ++d) acc[mi][ni][d] = 0.0f;

        #pragma unroll
        for (int kf = 0; kf < 16; ++kf) {
            uint32_t a[2][4];
            #pragma unroll
            for (int mi = 0; mi < 2; ++mi) {
                uint32_t row = (uint32_t)(wm * 32 + mi * 16 + (lane & 15));
                uint32_t kb  = (uint32_t)(kf * 32 + (lane >> 4) * 16);
                ldsm_x4(a[mi][0], a[mi][1], a[mi][2], a[mi][3], as32 + sw(row, kb));
            }
            uint32_t b[4][2];
            #pragma unroll
            for (int np = 0; np < 2; ++np) {
                uint32_t col = (uint32_t)(wn * 32 + np * 16 + (lane & 7) + ((lane >> 4) & 1) * 8);
                uint32_t kb  = (uint32_t)(kf * 32 + ((lane >> 3) & 1) * 16);
                uint32_t r0, r1, r2, r3;
                ldsm_x4(r0, r1, r2, r3, bbuf + sw(col, kb));
                b[2 * np][0] = r0; b[2 * np][1] = r1;
                b[2 * np + 1][0] = r2; b[2 * np + 1][1] = r3;
            }
            #pragma unroll
            for (int mi = 0; mi < 2; ++mi)
                #pragma unroll
                for (int ni = 0; ni < 4; ++ni)
                    mma16816(acc[mi][ni][0], acc[mi][ni][1], acc[mi][ni][2], acc[mi][ni][3],
                             a[mi][0], a[mi][1], a[mi][2], a[mi][3], b[ni][0], b[ni][1]);
        }

        // epilogue: approx top-2 per owned row
        const int colT = qBase + ct * 128 + wn * 32 + (lane & 3) * 2;
        #pragma unroll
        for (int mi = 0; mi < 2; ++mi)
            #pragma unroll
            for (int ni = 0; ni < 4; ++ni)
                #pragma unroll
                for (int d = 0; d < 4; ++d) {
                    float v = acc[mi][ni][d];
                    int   c = colT + ni * 8 + (d & 1);
                    int   s = mi * 2 + (d >> 1);
                    if (v > tv[s][0]) {
                        tv[s][1] = tv[s][0]; tix[s][1] = tix[s][0];
                        tv[s][0] = v;        tix[s][0] = c;
                    } else if (v > tv[s][1]) {
                        tv[s][1] = v;        tix[s][1] = c;
                    }
                }

        CP_WAIT0();
        __syncthreads();
    }

    // ---- CTA-level top-2 reduce (reuse A smem region) ----
    float* sval = (float*)(smem + (as32 - sb));
    int*   sidx = (int*)(sval + 128 * 32);
    const int own = wn * 4 + (lane & 3);
    #pragma unroll
    for (int s = 0; s < 4; ++s) {
        int rowL = wm * 32 + (s >> 1) * 16 + (s & 1) * 8 + (lane >> 2);
        sval[rowL * 32 + own * 2 + 0] = tv[s][0];
        sval[rowL * 32 + own * 2 + 1] = tv[s][1];
        sidx[rowL * 32 + own * 2 + 0] = tix[s][0];
        sidx[rowL * 32 + own * 2 + 1] = tix[s][1];
    }
    __syncthreads();
    if (tid < 128) {
        float v1 = -INFINITY, v2 = -INFINITY;
        int   i1 = 0x7fffffff, i2 = 0x7fffffff;
        #pragma unroll
        for (int t = 0; t < 32; ++t) {
            float v = sval[tid * 32 + t];
            int   i = sidx[tid * 32 + t];
            if (v > v1) { v2 = v1; i2 = i1; v1 = v; i1 = i; }
            else if (v > v2) { v2 = v; i2 = i; }
        }
        size_t o = (size_t)(rowBase + tid) * (2 * QS) + blockIdx.y * 2;
        g_c2val[o + 0] = v1; g_c2idx[o + 0] = i1;
        g_c2val[o + 1] = v2; g_c2idx[o + 1] = i2;
    }
}

// ============================================================
// Kernel 2: exact fp32 rescore of candidates -> g_gidx.
// One warp per row; 64 candidates; threshold approxmax - margin.
// ============================================================
__global__ void rescore_kernel(const float* __restrict__ emb,
                               const float* __restrict__ queue)
{
    int warp = (blockIdx.x * blockDim.x + threadIdx.x) >> 5;
    int lane = threadIdx.x & 31;
    if (warp >= B_TOT) return;

    size_t o = (size_t)warp * (2 * QS);
    float v0 = g_c2val[o + lane];
    float v1 = g_c2val[o + 32 + lane];
    int   i0 = g_c2idx[o + lane];
    int   i1 = g_c2idx[o + 32 + lane];

    float m = fmaxf(v0, v1);
    #pragma unroll
    for (int sh = 16; sh; sh >>= 1) m = fmaxf(m, __shfl_xor_sync(0xffffffffu, m, sh));
    const float thr = m - RESCORE_MARGIN;

    const float4* e4 = (const float4*)(emb + (size_t)warp * DDIM);
    float s0 = -INFINITY, s1 = -INFINITY;
    if (v0 >= thr) {
        const float4* q4 = (const float4*)(queue + (size_t)i0 * DDIM);
        float acc = 0.0f;
        #pragma unroll 8
        for (int k = 0; k < 64; ++k) {
            float4 a = e4[k], b = q4[k];
            acc = fmaf(a.x, b.x, acc); acc = fmaf(a.y, b.y, acc);
            acc = fmaf(a.z, b.z, acc); acc = fmaf(a.w, b.w, acc);
        }
        s0 = acc;
    }
    if (v1 >= thr) {
        const float4* q4 = (const float4*)(queue + (size_t)i1 * DDIM);
        float acc = 0.0f;
        #pragma unroll 8
        for (int k = 0; k < 64; ++k) {
            float4 a = e4[k], b = q4[k];
            acc = fmaf(a.x, b.x, acc); acc = fmaf(a.y, b.y, acc);
            acc = fmaf(a.z, b.z, acc); acc = fmaf(a.w, b.w, acc);
        }
        s1 = acc;
    }
    float bv = s0; int bi = i0;
    if (s1 > bv || (s1 == bv && i1 < bi)) { bv = s1; bi = i1; }
    #pragma unroll
    for (int sh = 16; sh; sh >>= 1) {
        float ov = __shfl_xor_sync(0xffffffffu, bv, sh);
        int   oi = __shfl_xor_sync(0xffffffffu, bi, sh);
        if (ov > bv || (ov == bv && oi < bi)) { bv = ov; bi = oi; }
    }
    if (lane == 0) g_gidx[warp] = bi;
}

// ============================================================
// Kernel 3: logits GEMM + online logsumexp partials (fp32 FFMA, from R1).
// ============================================================
__global__ __launch_bounds__(256, 1)
void logits_lse_kernel(const float* __restrict__ queue,
                       const float* __restrict__ preds)
{
    extern __shared__ float smemf[];
    float* As   = smemf;
    float* Bs   = smemf + 256 * LDA;
    float* redM = Bs + 2 * BK * LDA;
    float* redS = redM + BM * 16;

    const int tid = threadIdx.x;
    const int tx = tid & 15;
    const int ty = tid >> 4;
    const int dir      = blockIdx.z;
    const int rowBase  = blockIdx.x * BM;
    const int colBase  = blockIdx.y * NCOL;
    const int predBase = (dir == 0) ? HALF : 0;
    const int idxBase  = dir * HALF;

    #pragma unroll 4
    for (int m = 0; m < BM; ++m) {
        int qi = g_gidx[idxBase + rowBase + m];
        As[tid * LDA + m] = queue[(size_t)qi * DDIM + tid];
    }
    __syncthreads();

    const int bn  = tid >> 1;
    const int bks = (tid & 1) * 16;

    float lm[8], ls[8];
    #pragma unroll
    for (int r = 0; r < 8; ++r) { lm[r] = -INFINITY; ls[r] = 0.0f; }

    for (int qt = 0; qt < NCOL / 128; ++qt) {
        float acc[8][8];
        #pragma unroll
        for (int r = 0; r < 8; ++r)
            #pragma unroll
            for (int c = 0; c < 8; ++c) acc[r][c] = 0.0f;

        {
            const float* src = preds + (size_t)(predBase + colBase + qt * 128 + bn) * DDIM + bks;
            #pragma unroll
            for (int j = 0; j < 4; ++j) {
                float4 v = *(const float4*)(src + 4 * j);
                Bs[(bks + 4*j + 0) * LDA + bn] = v.x;
                Bs[(bks + 4*j + 1) * LDA + bn] = v.y;
                Bs[(bks + 4*j + 2) * LDA + bn] = v.z;
                Bs[(bks + 4*j + 3) * LDA + bn] = v.w;
            }
        }
        __syncthreads();

        for (int kb = 0; kb < DDIM / BK; ++kb) {
            float4 pre[4];
            const bool hasNext = (kb + 1) < (DDIM / BK);
            if (hasNext) {
                const float* src = preds + (size_t)(predBase + colBase + qt * 128 + bn) * DDIM
                                 + (kb + 1) * BK + bks;
                #pragma unroll
                for (int j = 0; j < 4; ++j) pre[j] = *(const float4*)(src + 4 * j);
            }
            const float* a_base = As + (kb * BK) * LDA + ty * 8;
            const float* b_base = Bs + (kb & 1) * BK * LDA + tx * 8;
            #pragma unroll
            for (int kk = 0; kk < BK; ++kk) {
                float4 a0 = *(const float4*)(a_base + kk * LDA);
                float4 a1 = *(const float4*)(a_base + kk * LDA + 4);
                float4 b0 = *(const float4*)(b_base + kk * LDA);
                float4 b1 = *(const float4*)(b_base + kk * LDA + 4);
                float av[8] = {a0.x,a0.y,a0.z,a0.w,a1.x,a1.y,a1.z,a1.w};
                float bv[8] = {b0.x,b0.y,b0.z,b0.w,b1.x,b1.y,b1.z,b1.w};
                #pragma unroll
                for (int r = 0; r < 8; ++r)
                    #pragma unroll
                    for (int c = 0; c < 8; ++c)
                        acc[r][c] = fmaf(av[r], bv[c], acc[r][c]);
            }
            if (hasNext) {
                float* dst = Bs + ((kb + 1) & 1) * BK * LDA;
                #pragma unroll
                for (int j = 0; j < 4; ++j) {
                    dst[(bks + 4*j + 0) * LDA + bn] = pre[j].x;
                    dst[(bks + 4*j + 1) * LDA + bn] = pre[j].y;
                    dst[(bks + 4*j + 2) * LDA + bn] = pre[j].z;
                    dst[(bks + 4*j + 3) * LDA + bn] = pre[j].w;
                }
            }
            __syncthreads();
        }

        #pragma unroll
        for (int r = 0; r < 8; ++r)
            #pragma unroll
            for (int c = 0; c < 8; ++c) {
                float x = acc[r][c] * INV_T;
                if (x > lm[r]) {
                    ls[r] = ls[r] * expf(lm[r] - x) + 1.0f;
                    lm[r] = x;
                } else {
                    ls[r] += expf(x - lm[r]);
                }
            }
    }

    #pragma unroll
    for (int r = 0; r < 8; ++r) {
        redM[(ty * 8 + r) * 16 + tx] = lm[r];
        redS[(ty * 8 + r) * 16 + tx] = ls[r];
    }
    __syncthreads();
    if (tid < BM) {
        float M = -INFINITY;
        #pragma unroll
        for (int t = 0; t < 16; ++t) M = fmaxf(M, redM[tid * 16 + t]);
        float S = 0.0f;
        #pragma unroll
        for (int t = 0; t < 16; ++t) S += redS[tid * 16 + t] * expf(redM[tid * 16 + t] - M);
        int row = rowBase + tid;
        g_lsem[(size_t)(idxBase + row) * CS + blockIdx.y] = M;
        g_lses[(size_t)(idxBase + row) * CS + blockIdx.y] = S;
    }
}

// ============================================================
// Kernel 4: per-row loss = logsumexp - diagonal logit.
// ============================================================
__global__ void ce_finalize_kernel(const float* __restrict__ queue,
                                   const float* __restrict__ preds)
{
    int warp = (blockIdx.x * blockDim.x + threadIdx.x) >> 5;
    int lane = threadIdx.x & 31;
    #pragma unroll
    for (int rr = 0; rr < 4; ++rr) {
        int ridx = warp * 4 + rr;
        if (ridx >= 2 * HALF) return;
        int dir = ridx >> 11;
        int row = ridx & (HALF - 1);
        int qi  = g_gidx[dir * HALF + row];
        const float* a = queue + (size_t)qi * DDIM;
        const float* b = preds + (size_t)(((dir == 0) ? HALF : 0) + row) * DDIM;
        float p = 0.0f;
        for (int k = lane; k < DDIM; k += 32) p = fmaf(a[k], b[k], p);
        #pragma unroll
        for (int o = 16; o; o >>= 1) p += __shfl_xor_sync(0xffffffffu, p, o);
        if (lane == 0) {
            float M = -INFINITY;
            #pragma unroll
            for (int t = 0; t < CS; ++t) M = fmaxf(M, g_lsem[(size_t)ridx * CS + t]);
            float S = 0.0f;
            #pragma unroll
            for (int t = 0; t < CS; ++t)
                S += g_lses[(size_t)ridx * CS + t] * expf(g_lsem[(size_t)ridx * CS + t] - M);
            float lse = M + logf(S);
            g_rowloss[ridx] = lse - p * INV_T;
        }
    }
}

// ============================================================
// Kernel 5: final reduction -> scalar loss
// ============================================================
__global__ void final_sum_kernel(float* __restrict__ out)
{
    __shared__ float sm0[256], sm1[256];
    int tid = threadIdx.x;
    float s0 = 0.0f, s1 = 0.0f;
    for (int i = tid; i < HALF; i += 256) {
        s0 += g_rowloss[i];
        s1 += g_rowloss[HALF + i];
    }
    sm0[tid] = s0; sm1[tid] = s1;
    __syncthreads();
    for (int o = 128; o; o >>= 1) {
        if (tid < o) { sm0[tid] += sm0[tid + o]; sm1[tid] += sm1[tid + o]; }
        __syncthreads();
    }
    if (tid == 0)
        out[0] = 0.5f * (sm0[0] / (float)HALF + sm1[0] / (float)HALF);
}

// ============================================================
extern "C" void kernel_launch(void* const* d_in, const int* in_sizes, int n_in,
                              void* d_out, int out_size)
{
    const float* emb   = (const float*)d_in[0];
    const float* preds = (const float*)d_in[1];
    const float* queue = (const float*)d_in[2];
    float* out = (float*)d_out;

    __nv_bfloat16 *qhi, *ehi;
    cudaGetSymbolAddress((void**)&qhi, g_qhi);
    cudaGetSymbolAddress((void**)&ehi, g_ehi);

    to_bf16_kernel<<<(QTOT * DDIM / 4 + 255) / 256, 256>>>(queue, qhi, QTOT * DDIM / 4);
    to_bf16_kernel<<<(B_TOT * DDIM / 4 + 255) / 256, 256>>>(emb, ehi, B_TOT * DDIM / 4);

    const size_t smemArg = 1024 + 65536 + 131072;
    cudaFuncSetAttribute(argmax_mma_kernel,
                         cudaFuncAttributeMaxDynamicSharedMemorySize, (int)smemArg);
    argmax_mma_kernel<<<dim3(B_TOT / 128, QS), 512, smemArg>>>();

    rescore_kernel<<<B_TOT / 8, 256>>>(emb, queue);

    const size_t smemLog = (size_t)(256 * LDA + 2 * BK * LDA) * sizeof(float)
                         + (size_t)BM * 16 * 2 * sizeof(float);
    cudaFuncSetAttribute(logits_lse_kernel,
                         cudaFuncAttributeMaxDynamicSharedMemorySize, (int)smemLog);
    logits_lse_kernel<<<dim3(HALF / BM, CS, 2), 256, smemLog>>>(queue, preds);

    ce_finalize_kernel<<<128, 256>>>(queue, preds);
    final_sum_kernel<<<1, 256>>>(out);
}

// round 7
// speedup vs baseline: 7.4263x; 1.0463x over previous
#include <cuda_runtime.h>
#include <cuda_bf16.h>
#include <math.h>
#include <stdint.h>

// NNclrInfoNCECriterion on GB300 (compute_103 PTX -> legacy mma.sync path).
// Stage 1: bf16 mma.sync sim GEMM, per-row approx top-2 -> exact fp32 rescore -> argmax.
// Stage 2: bf16 mma.sync logits GEMM + fp32 online LSE; exact fp32 diagonal in finalize.

#define B_TOT 4096
#define HALF  2048
#define DDIM  256
#define QTOT  65536
#define QS    32
#define QCHUNK (QTOT/QS)     // 2048
#define NTILE  (QCHUNK/128)  // 16 col-tiles per CTA
#define CS 4
#define NCOL (HALF/CS)       // 512
#define NTILE_LOG (NCOL/128) // 4
#define INV_T 10.0f
#define RESCORE_MARGIN 0.02f

// ---------------- scratch globals ----------------
__device__ __nv_bfloat16 g_qhi[(size_t)QTOT * DDIM];
__device__ __nv_bfloat16 g_ehi[(size_t)B_TOT * DDIM];
__device__ __nv_bfloat16 g_phi[(size_t)B_TOT * DDIM];
__device__ float g_c2val[(size_t)B_TOT * 2 * QS];
__device__ int   g_c2idx[(size_t)B_TOT * 2 * QS];
__device__ int   g_gidx[B_TOT];
__device__ float g_lsem[2 * HALF * CS];
__device__ float g_lses[2 * HALF * CS];
__device__ float g_rowloss[2 * HALF];

// ---------------- helpers ----------------
__device__ __forceinline__ uint32_t smem_to_u32(const void* p) {
    uint32_t a;
    asm("{ .reg .u64 t; cvta.to.shared.u64 t, %1; cvt.u32.u64 %0, t; }" : "=r"(a) : "l"(p));
    return a;
}
__device__ __forceinline__ void cp_async16(uint32_t dst, const void* src) {
    asm volatile("cp.async.cg.shared.global [%0], [%1], 16;" :: "r"(dst), "l"(src) : "memory");
}
#define CP_COMMIT() asm volatile("cp.async.commit_group;" ::: "memory")
#define CP_WAIT0()  asm volatile("cp.async.wait_group 0;" ::: "memory")

__device__ __forceinline__ void ldsm_x4(uint32_t& r0, uint32_t& r1, uint32_t& r2, uint32_t& r3,
                                        uint32_t addr) {
    asm volatile("ldmatrix.sync.aligned.m8n8.x4.shared.b16 {%0,%1,%2,%3}, [%4];"
                 : "=r"(r0), "=r"(r1), "=r"(r2), "=r"(r3) : "r"(addr));
}
__device__ __forceinline__ void mma16816(float& d0, float& d1, float& d2, float& d3,
                                         uint32_t a0, uint32_t a1, uint32_t a2, uint32_t a3,
                                         uint32_t b0, uint32_t b1) {
    asm volatile("mma.sync.aligned.m16n8k16.row.col.f32.bf16.bf16.f32 "
                 "{%0,%1,%2,%3}, {%4,%5,%6,%7}, {%8,%9}, {%0,%1,%2,%3};"
                 : "+f"(d0), "+f"(d1), "+f"(d2), "+f"(d3)
                 : "r"(a0), "r"(a1), "r"(a2), "r"(a3), "r"(b0), "r"(b1));
}
// swizzled byte offset inside a [rows x 256 bf16] tile (512 B rows)
__device__ __forceinline__ uint32_t sw(uint32_t row, uint32_t kb) {
    return row * 512u + (kb ^ ((row & 7u) << 4));
}

// ============================================================
// fp32 -> bf16 conversion
// ============================================================
__global__ void to_bf16_kernel(const float* __restrict__ src,
                               __nv_bfloat16* __restrict__ dst, int n4)
{
    int i = blockIdx.x * blockDim.x + threadIdx.x;
    if (i < n4) {
        float4 v = ((const float4*)src)[i];
        ((__nv_bfloat162*)dst)[2 * i]     = __floats2bfloat162_rn(v.x, v.y);
        ((__nv_bfloat162*)dst)[2 * i + 1] = __floats2bfloat162_rn(v.z, v.w);
    }
}

// ============================================================
// Kernel 1: bf16 mma.sync sim GEMM + per-row approx top-2.
// 256 threads, 8 warps (4 x 2 warp grid), warp tile 32 rows x 64 cols.
// CTA tile M=128 x N=128, K=256; A smem-resident, B double-buffered cp.async.
// ============================================================
__global__ __launch_bounds__(256, 1)
void argmax_mma_kernel()
{
    extern __shared__ char smem[];
    const uint32_t sb   = smem_to_u32(smem);
    const uint32_t as32 = (sb + 1023u) & ~1023u;   // A: 64KB
    const uint32_t bs32 = as32 + 65536u;           // B: 2 x 64KB

    const int tid  = threadIdx.x;
    const int lane = tid & 31;
    const int w    = tid >> 5;
    const int wm   = w >> 1;          // 0..3 (32-row slab)
    const int wn   = w & 1;           // 0..1 (64-col slab)
    const int rowBase = blockIdx.x * 128;
    const int qBase   = blockIdx.y * QCHUNK;

    // ---- async load A (128x256 bf16) + B tile 0 ----
    #pragma unroll
    for (int i = 0; i < 16; ++i) {
        int c = i * 256 + tid;
        uint32_t row = (uint32_t)(c >> 5), k16 = (uint32_t)(c & 31);
        cp_async16(as32 + sw(row, k16 * 16),
                   (const char*)(g_ehi + (size_t)(rowBase + row) * DDIM) + k16 * 16);
    }
    #pragma unroll
    for (int i = 0; i < 16; ++i) {
        int c = i * 256 + tid;
        uint32_t row = (uint32_t)(c >> 5), k16 = (uint32_t)(c & 31);
        cp_async16(bs32 + sw(row, k16 * 16),
                   (const char*)(g_qhi + (size_t)(qBase + row) * DDIM) + k16 * 16);
    }
    CP_COMMIT();
    CP_WAIT0();
    __syncthreads();

    float tv[4][2];
    int   tix[4][2];
    #pragma unroll
    for (int s = 0; s < 4; ++s) {
        tv[s][0] = -INFINITY; tv[s][1] = -INFINITY;
        tix[s][0] = 0x7fffffff; tix[s][1] = 0x7fffffff;
    }

    for (int ct = 0; ct < NTILE; ++ct) {
        if (ct + 1 < NTILE) {
            const uint32_t nbuf = bs32 + (uint32_t)((ct + 1) & 1) * 65536u;
            #pragma unroll
            for (int i = 0; i < 16; ++i) {
                int c = i * 256 + tid;
                uint32_t row = (uint32_t)(c >> 5), k16 = (uint32_t)(c & 31);
                cp_async16(nbuf + sw(row, k16 * 16),
                           (const char*)(g_qhi + (size_t)(qBase + (ct + 1) * 128 + row) * DDIM) + k16 * 16);
            }
            CP_COMMIT();
        }

        const uint32_t bbuf = bs32 + (uint32_t)(ct & 1) * 65536u;
        float acc[2][8][4];
        #pragma unroll
        for (int mi = 0; mi < 2; ++mi)
            #pragma unroll
            for (int ni = 0; ni < 8; ++ni)
                #pragma unroll
                for (int d = 0; d < 4; ++d) acc[mi][ni][d] = 0.0f;

        #pragma unroll
        for (int kf = 0; kf < 16; ++kf) {
            uint32_t a[2][4];
            #pragma unroll
            for (int mi = 0; mi < 2; ++mi) {
                uint32_t row = (uint32_t)(wm * 32 + mi * 16 + (lane & 15));
                uint32_t kb  = (uint32_t)(kf * 32 + (lane >> 4) * 16);
                ldsm_x4(a[mi][0], a[mi][1], a[mi][2], a[mi][3], as32 + sw(row, kb));
            }
            uint32_t b[8][2];
            #pragma unroll
            for (int np = 0; np < 4; ++np) {
                uint32_t col = (uint32_t)(wn * 64 + np * 16 + (lane & 7) + ((lane >> 4) & 1) * 8);
                uint32_t kb  = (uint32_t)(kf * 32 + ((lane >> 3) & 1) * 16);
                uint32_t r0, r1, r2, r3;
                ldsm_x4(r0, r1, r2, r3, bbuf + sw(col, kb));
                b[2 * np][0] = r0; b[2 * np][1] = r1;
                b[2 * np + 1][0] = r2; b[2 * np + 1][1] = r3;
            }
            #pragma unroll
            for (int mi = 0; mi < 2; ++mi)
                #pragma unroll
                for (int ni = 0; ni < 8; ++ni)
                    mma16816(acc[mi][ni][0], acc[mi][ni][1], acc[mi][ni][2], acc[mi][ni][3],
                             a[mi][0], a[mi][1], a[mi][2], a[mi][3], b[ni][0], b[ni][1]);
        }

        // epilogue: approx top-2 per owned row-slot
        const int colT = qBase + ct * 128 + wn * 64 + (lane & 3) * 2;
        #pragma unroll
        for (int mi = 0; mi < 2; ++mi)
            #pragma unroll
            for (int ni = 0; ni < 8; ++ni)
                #pragma unroll
                for (int d = 0; d < 4; ++d) {
                    float v = acc[mi][ni][d];
                    int   c = colT + ni * 8 + (d & 1);
                    int   s = mi * 2 + (d >> 1);
                    if (v > tv[s][0]) {
                        tv[s][1] = tv[s][0]; tix[s][1] = tix[s][0];
                        tv[s][0] = v;        tix[s][0] = c;
                    } else if (v > tv[s][1]) {
                        tv[s][1] = v;        tix[s][1] = c;
                    }
                }

        CP_WAIT0();
        __syncthreads();
    }

    // ---- CTA top-2 reduce (reuse A smem) : 8 contributors x 2 per row ----
    float* sval = (float*)(smem + (as32 - sb));
    int*   sidx = (int*)(sval + 128 * 16);
    const int cont = wn * 4 + (lane & 3);
    #pragma unroll
    for (int s = 0; s < 4; ++s) {
        int rowL = wm * 32 + (s >> 1) * 16 + (s & 1) * 8 + (lane >> 2);
        sval[rowL * 16 + cont * 2 + 0] = tv[s][0];
        sval[rowL * 16 + cont * 2 + 1] = tv[s][1];
        sidx[rowL * 16 + cont * 2 + 0] = tix[s][0];
        sidx[rowL * 16 + cont * 2 + 1] = tix[s][1];
    }
    __syncthreads();
    if (tid < 128) {
        float v1 = -INFINITY, v2 = -INFINITY;
        int   i1 = 0x7fffffff, i2 = 0x7fffffff;
        #pragma unroll
        for (int t = 0; t < 16; ++t) {
            float v = sval[tid * 16 + t];
            int   i = sidx[tid * 16 + t];
            if (v > v1) { v2 = v1; i2 = i1; v1 = v; i1 = i; }
            else if (v > v2) { v2 = v; i2 = i; }
        }
        size_t o = (size_t)(rowBase + tid) * (2 * QS) + blockIdx.y * 2;
        g_c2val[o + 0] = v1; g_c2idx[o + 0] = i1;
        g_c2val[o + 1] = v2; g_c2idx[o + 1] = i2;
    }
}

// ============================================================
// Kernel 2: exact fp32 rescore of 64 candidates -> g_gidx.
// ============================================================
__global__ void rescore_kernel(const float* __restrict__ emb,
                               const float* __restrict__ queue)
{
    int warp = (blockIdx.x * blockDim.x + threadIdx.x) >> 5;
    int lane = threadIdx.x & 31;
    if (warp >= B_TOT) return;

    size_t o = (size_t)warp * (2 * QS);
    float v0 = g_c2val[o + lane];
    float v1 = g_c2val[o + 32 + lane];
    int   i0 = g_c2idx[o + lane];
    int   i1 = g_c2idx[o + 32 + lane];

    float m = fmaxf(v0, v1);
    #pragma unroll
    for (int sh = 16; sh; sh >>= 1) m = fmaxf(m, __shfl_xor_sync(0xffffffffu, m, sh));
    const float thr = m - RESCORE_MARGIN;

    const float4* e4 = (const float4*)(emb + (size_t)warp * DDIM);
    float s0 = -INFINITY, s1 = -INFINITY;
    if (v0 >= thr) {
        const float4* q4 = (const float4*)(queue + (size_t)i0 * DDIM);
        float acc = 0.0f;
        #pragma unroll 8
        for (int k = 0; k < 64; ++k) {
            float4 a = e4[k], b = q4[k];
            acc = fmaf(a.x, b.x, acc); acc = fmaf(a.y, b.y, acc);
            acc = fmaf(a.z, b.z, acc); acc = fmaf(a.w, b.w, acc);
        }
        s0 = acc;
    }
    if (v1 >= thr) {
        const float4* q4 = (const float4*)(queue + (size_t)i1 * DDIM);
        float acc = 0.0f;
        #pragma unroll 8
        for (int k = 0; k < 64; ++k) {
            float4 a = e4[k], b = q4[k];
            acc = fmaf(a.x, b.x, acc); acc = fmaf(a.y, b.y, acc);
            acc = fmaf(a.z, b.z, acc); acc = fmaf(a.w, b.w, acc);
        }
        s1 = acc;
    }
    float bv = s0; int bi = i0;
    if (s1 > bv || (s1 == bv && i1 < bi)) { bv = s1; bi = i1; }
    #pragma unroll
    for (int sh = 16; sh; sh >>= 1) {
        float ov = __shfl_xor_sync(0xffffffffu, bv, sh);
        int   oi = __shfl_xor_sync(0xffffffffu, bi, sh);
        if (ov > bv || (ov == bv && oi < bi)) { bv = ov; bi = oi; }
    }
    if (lane == 0) g_gidx[warp] = bi;
}

// ============================================================
// Kernel 3: bf16 mma.sync logits GEMM + fp32 online logsumexp partials.
// grid (16 row-tiles, CS colgroups, 2 dirs); 256 thr, same tiling as kernel 1.
// A = queue[gidx] gathered bf16; B = preds bf16.
// ============================================================
__global__ __launch_bounds__(256, 1)
void logits_mma_kernel()
{
    extern __shared__ char smem[];
    const uint32_t sb   = smem_to_u32(smem);
    const uint32_t as32 = (sb + 1023u) & ~1023u;
    const uint32_t bs32 = as32 + 65536u;

    const int tid  = threadIdx.x;
    const int lane = tid & 31;
    const int w    = tid >> 5;
    const int wm   = w >> 1;
    const int wn   = w & 1;
    const int dir      = blockIdx.z;
    const int rowBase  = blockIdx.x * 128;
    const int colBase  = blockIdx.y * NCOL;
    const int predBase = (dir == 0) ? HALF : 0;
    const int idxBase  = dir * HALF;

    // ---- gather A rows (nn in bf16) + B tile 0 ----
    #pragma unroll
    for (int i = 0; i < 16; ++i) {
        int c = i * 256 + tid;
        uint32_t row = (uint32_t)(c >> 5), k16 = (uint32_t)(c & 31);
        int qi = g_gidx[idxBase + rowBase + (int)row];
        cp_async16(as32 + sw(row, k16 * 16),
                   (const char*)(g_qhi + (size_t)qi * DDIM) + k16 * 16);
    }
    #pragma unroll
    for (int i = 0; i < 16; ++i) {
        int c = i * 256 + tid;
        uint32_t row = (uint32_t)(c >> 5), k16 = (uint32_t)(c & 31);
        cp_async16(bs32 + sw(row, k16 * 16),
                   (const char*)(g_phi + (size_t)(predBase + colBase + row) * DDIM) + k16 * 16);
    }
    CP_COMMIT();
    CP_WAIT0();
    __syncthreads();

    float lm[4], ls[4];
    #pragma unroll
    for (int s = 0; s < 4; ++s) { lm[s] = -INFINITY; ls[s] = 0.0f; }

    for (int ct = 0; ct < NTILE_LOG; ++ct) {
        if (ct + 1 < NTILE_LOG) {
            const uint32_t nbuf = bs32 + (uint32_t)((ct + 1) & 1) * 65536u;
            #pragma unroll
            for (int i = 0; i < 16; ++i) {
                int c = i * 256 + tid;
                uint32_t row = (uint32_t)(c >> 5), k16 = (uint32_t)(c & 31);
                cp_async16(nbuf + sw(row, k16 * 16),
                           (const char*)(g_phi + (size_t)(predBase + colBase + (ct + 1) * 128 + row) * DDIM) + k16 * 16);
            }
            CP_COMMIT();
        }

        const uint32_t bbuf = bs32 + (uint32_t)(ct & 1) * 65536u;
        float acc[2][8][4];
        #pragma unroll
        for (int mi = 0; mi < 2; ++mi)
            #pragma unroll
            for (int ni = 0; ni < 8; ++ni)
                #pragma unroll
                for (int d = 0; d < 4; ++d) acc[mi][ni][d] = 0.0f;

        #pragma unroll
        for (int kf = 0; kf < 16; ++kf) {
            uint32_t a[2][4];
            #pragma unroll
            for (int mi = 0; mi < 2; ++mi) {
                uint32_t row = (uint32_t)(wm * 32 + mi * 16 + (lane & 15));
                uint32_t kb  = (uint32_t)(kf * 32 + (lane >> 4) * 16);
                ldsm_x4(a[mi][0], a[mi][1], a[mi][2], a[mi][3], as32 + sw(row, kb));
            }
            uint32_t b[8][2];
            #pragma unroll
            for (int np = 0; np < 4; ++np) {
                uint32_t col = (uint32_t)(wn * 64 + np * 16 + (lane & 7) + ((lane >> 4) & 1) * 8);
                uint32_t kb  = (uint32_t)(kf * 32 + ((lane >> 3) & 1) * 16);
                uint32_t r0, r1, r2, r3;
                ldsm_x4(r0, r1, r2, r3, bbuf + sw(col, kb));
                b[2 * np][0] = r0; b[2 * np][1] = r1;
                b[2 * np + 1][0] = r2; b[2 * np + 1][1] = r3;
            }
            #pragma unroll
            for (int mi = 0; mi < 2; ++mi)
                #pragma unroll
                for (int ni = 0; ni < 8; ++ni)
                    mma16816(acc[mi][ni][0], acc[mi][ni][1], acc[mi][ni][2], acc[mi][ni][3],
                             a[mi][0], a[mi][1], a[mi][2], a[mi][3], b[ni][0], b[ni][1]);
        }

        // epilogue: online logsumexp (fp32) over this tile's columns
        #pragma unroll
        for (int mi = 0; mi < 2; ++mi)
            #pragma unroll
            for (int ni = 0; ni < 8; ++ni)
                #pragma unroll
                for (int d = 0; d < 4; ++d) {
                    float x = acc[mi][ni][d] * INV_T;
                    int   s = mi * 2 + (d >> 1);
                    if (x > lm[s]) {
                        ls[s] = ls[s] * expf(lm[s] - x) + 1.0f;
                        lm[s] = x;
                    } else {
                        ls[s] += expf(x - lm[s]);
                    }
                }

        CP_WAIT0();
        __syncthreads();
    }

    // ---- CTA LSE reduce: 8 contributors per row ----
    float* sM = (float*)(smem + (as32 - sb));
    float* sS = sM + 128 * 8;
    const int cont = wn * 4 + (lane & 3);
    #pragma unroll
    for (int s = 0; s < 4; ++s) {
        int rowL = wm * 32 + (s >> 1) * 16 + (s & 1) * 8 + (lane >> 2);
        sM[rowL * 8 + cont] = lm[s];
        sS[rowL * 8 + cont] = ls[s];
    }
    __syncthreads();
    if (tid < 128) {
        float M = -INFINITY;
        #pragma unroll
        for (int t = 0; t < 8; ++t) M = fmaxf(M, sM[tid * 8 + t]);
        float S = 0.0f;
        #pragma unroll
        for (int t = 0; t < 8; ++t) S += sS[tid * 8 + t] * expf(sM[tid * 8 + t] - M);
        int row = rowBase + tid;
        g_lsem[(size_t)(idxBase + row) * CS + blockIdx.y] = M;
        g_lses[(size_t)(idxBase + row) * CS + blockIdx.y] = S;
    }
}

// ============================================================
// Kernel 4: per-row loss = logsumexp - exact fp32 diagonal logit.
// ============================================================
__global__ void ce_finalize_kernel(const float* __restrict__ queue,
                                   const float* __restrict__ preds)
{
    int warp = (blockIdx.x * blockDim.x + threadIdx.x) >> 5;
    int lane = threadIdx.x & 31;
    #pragma unroll
    for (int rr = 0; rr < 4; ++rr) {
        int ridx = warp * 4 + rr;
        if (ridx >= 2 * HALF) return;
        int dir = ridx >> 11;
        int row = ridx & (HALF - 1);
        int qi  = g_gidx[dir * HALF + row];
        const float* a = queue + (size_t)qi * DDIM;
        const float* b = preds + (size_t)(((dir == 0) ? HALF : 0) + row) * DDIM;
        float p = 0.0f;
        for (int k = lane; k < DDIM; k += 32) p = fmaf(a[k], b[k], p);
        #pragma unroll
        for (int o = 16; o; o >>= 1) p += __shfl_xor_sync(0xffffffffu, p, o);
        if (lane == 0) {
            float M = -INFINITY;
            #pragma unroll
            for (int t = 0; t < CS; ++t) M = fmaxf(M, g_lsem[(size_t)ridx * CS + t]);
            float S = 0.0f;
            #pragma unroll
            for (int t = 0; t < CS; ++t)
                S += g_lses[(size_t)ridx * CS + t] * expf(g_lsem[(size_t)ridx * CS + t] - M);
            float lse = M + logf(S);
            g_rowloss[ridx] = lse - p * INV_T;
        }
    }
}

// ============================================================
// Kernel 5: final reduction -> scalar loss
// ============================================================
__global__ void final_sum_kernel(float* __restrict__ out)
{
    __shared__ float sm0[256], sm1[256];
    int tid = threadIdx.x;
    float s0 = 0.0f, s1 = 0.0f;
    for (int i = tid; i < HALF; i += 256) {
        s0 += g_rowloss[i];
        s1 += g_rowloss[HALF + i];
    }
    sm0[tid] = s0; sm1[tid] = s1;
    __syncthreads();
    for (int o = 128; o; o >>= 1) {
        if (tid < o) { sm0[tid] += sm0[tid + o]; sm1[tid] += sm1[tid + o]; }
        __syncthreads();
    }
    if (tid == 0)
        out[0] = 0.5f * (sm0[0] / (float)HALF + sm1[0] / (float)HALF);
}

// ============================================================
extern "C" void kernel_launch(void* const* d_in, const int* in_sizes, int n_in,
                              void* d_out, int out_size)
{
    const float* emb   = (const float*)d_in[0];
    const float* preds = (const float*)d_in[1];
    const float* queue = (const float*)d_in[2];
    float* out = (float*)d_out;

    __nv_bfloat16 *qhi, *ehi, *phi;
    cudaGetSymbolAddress((void**)&qhi, g_qhi);
    cudaGetSymbolAddress((void**)&ehi, g_ehi);
    cudaGetSymbolAddress((void**)&phi, g_phi);

    to_bf16_kernel<<<(QTOT * DDIM / 4 + 255) / 256, 256>>>(queue, qhi, QTOT * DDIM / 4);
    to_bf16_kernel<<<(B_TOT * DDIM / 4 + 255) / 256, 256>>>(emb,   ehi, B_TOT * DDIM / 4);
    to_bf16_kernel<<<(B_TOT * DDIM / 4 + 255) / 256, 256>>>(preds, phi, B_TOT * DDIM / 4);

    const size_t smemArg = 1024 + 65536 + 131072;
    cudaFuncSetAttribute(argmax_mma_kernel,
                         cudaFuncAttributeMaxDynamicSharedMemorySize, (int)smemArg);
    argmax_mma_kernel<<<dim3(B_TOT / 128, QS), 256, smemArg>>>();

    rescore_kernel<<<B_TOT / 8, 256>>>(emb, queue);

    cudaFuncSetAttribute(logits_mma_kernel,
                         cudaFuncAttributeMaxDynamicSharedMemorySize, (int)smemArg);
    logits_mma_kernel<<<dim3(HALF / 128, CS, 2), 256, smemArg>>>();

    ce_finalize_kernel<<<128, 256>>>(queue, preds);
    final_sum_kernel<<<1, 256>>>(out);
}

// round 8
// speedup vs baseline: 8.0888x; 1.0892x over previous
#include <cuda_runtime.h>
#include <cuda_bf16.h>
#include <math.h>
#include <stdint.h>

// NNclrInfoNCECriterion on GB300 (compute_103 PTX -> legacy mma.sync path).
// Stage 1: bf16 mma.sync sim GEMM, per-row approx top-2 -> exact fp32 rescore -> argmax.
// Stage 2: bf16 mma.sync logits GEMM + fp32 online LSE; exact fp32 diagonal in finalize.

#define B_TOT 4096
#define HALF  2048
#define DDIM  256
#define QTOT  65536
#define QS    32
#define QCHUNK (QTOT/QS)     // 2048
#define NTILE  (QCHUNK/128)  // 16 col-tiles per CTA
#define CS 4
#define NCOL (HALF/CS)       // 512
#define NTILE_LOG (NCOL/128) // 4
#define INV_T 10.0f
#define RESCORE_MARGIN 0.02f

// ---------------- scratch globals ----------------
__device__ __nv_bfloat16 g_qhi[(size_t)QTOT * DDIM];
__device__ __nv_bfloat16 g_ehi[(size_t)B_TOT * DDIM];
__device__ __nv_bfloat16 g_phi[(size_t)B_TOT * DDIM];
__device__ float g_c2val[(size_t)B_TOT * 2 * QS];
__device__ int   g_c2idx[(size_t)B_TOT * 2 * QS];
__device__ int   g_gidx[B_TOT];
__device__ float g_lsem[2 * HALF * CS];
__device__ float g_lses[2 * HALF * CS];
__device__ float g_rowloss[2 * HALF];

// ---------------- helpers ----------------
__device__ __forceinline__ uint32_t smem_to_u32(const void* p) {
    uint32_t a;
    asm("{ .reg .u64 t; cvta.to.shared.u64 t, %1; cvt.u32.u64 %0, t; }" : "=r"(a) : "l"(p));
    return a;
}
__device__ __forceinline__ void cp_async16(uint32_t dst, const void* src) {
    asm volatile("cp.async.cg.shared.global [%0], [%1], 16;" :: "r"(dst), "l"(src) : "memory");
}
#define CP_COMMIT() asm volatile("cp.async.commit_group;" ::: "memory")
#define CP_WAIT0()  asm volatile("cp.async.wait_group 0;" ::: "memory")

__device__ __forceinline__ void ldsm_x4(uint32_t& r0, uint32_t& r1, uint32_t& r2, uint32_t& r3,
                                        uint32_t addr) {
    asm volatile("ldmatrix.sync.aligned.m8n8.x4.shared.b16 {%0,%1,%2,%3}, [%4];"
                 : "=r"(r0), "=r"(r1), "=r"(r2), "=r"(r3) : "r"(addr));
}
__device__ __forceinline__ void mma16816(float& d0, float& d1, float& d2, float& d3,
                                         uint32_t a0, uint32_t a1, uint32_t a2, uint32_t a3,
                                         uint32_t b0, uint32_t b1) {
    asm volatile("mma.sync.aligned.m16n8k16.row.col.f32.bf16.bf16.f32 "
                 "{%0,%1,%2,%3}, {%4,%5,%6,%7}, {%8,%9}, {%0,%1,%2,%3};"
                 : "+f"(d0), "+f"(d1), "+f"(d2), "+f"(d3)
                 : "r"(a0), "r"(a1), "r"(a2), "r"(a3), "r"(b0), "r"(b1));
}
// swizzled byte offset inside a [rows x 256 bf16] tile (512 B rows)
__device__ __forceinline__ uint32_t sw(uint32_t row, uint32_t kb) {
    return row * 512u + (kb ^ ((row & 7u) << 4));
}

// fragment loads for the 4x4 warp grid (warp tile 32 rows x 32 cols), one 16-k step
__device__ __forceinline__ void load_a_frags(uint32_t as32, int kf, int wm, int lane,
                                             uint32_t a[2][4]) {
    #pragma unroll
    for (int mi = 0; mi < 2; ++mi) {
        uint32_t row = (uint32_t)(wm * 32 + mi * 16 + (lane & 15));
        uint32_t kb  = (uint32_t)(kf * 32 + (lane >> 4) * 16);
        ldsm_x4(a[mi][0], a[mi][1], a[mi][2], a[mi][3], as32 + sw(row, kb));
    }
}
__device__ __forceinline__ void load_b_frags(uint32_t bbuf, int kf, int wn, int lane,
                                             uint32_t b[4][2]) {
    #pragma unroll
    for (int np = 0; np < 2; ++np) {
        uint32_t col = (uint32_t)(wn * 32 + np * 16 + (lane & 7) + ((lane >> 4) & 1) * 8);
        uint32_t kb  = (uint32_t)(kf * 32 + ((lane >> 3) & 1) * 16);
        uint32_t r0, r1, r2, r3;
        ldsm_x4(r0, r1, r2, r3, bbuf + sw(col, kb));
        b[2 * np][0] = r0; b[2 * np][1] = r1;
        b[2 * np + 1][0] = r2; b[2 * np + 1][1] = r3;
    }
}

// ============================================================
// fp32 -> bf16 conversion
// ============================================================
__global__ void to_bf16_kernel(const float* __restrict__ src,
                               __nv_bfloat16* __restrict__ dst, int n4)
{
    int i = blockIdx.x * blockDim.x + threadIdx.x;
    if (i < n4) {
        float4 v = ((const float4*)src)[i];
        ((__nv_bfloat162*)dst)[2 * i]     = __floats2bfloat162_rn(v.x, v.y);
        ((__nv_bfloat162*)dst)[2 * i + 1] = __floats2bfloat162_rn(v.z, v.w);
    }
}

// ============================================================
// Kernel 1: bf16 mma.sync sim GEMM + per-row approx top-2.
// 512 threads, 16 warps (4x4 grid), warp tile 32x32, fragment double-buffer.
// CTA tile M=128 x N=128, K=256; A smem-resident, B double-buffered cp.async.
// ============================================================
__global__ __launch_bounds__(512, 1)
void argmax_mma_kernel()
{
    extern __shared__ char smem[];
    const uint32_t sb   = smem_to_u32(smem);
    const uint32_t as32 = (sb + 1023u) & ~1023u;   // A: 64KB
    const uint32_t bs32 = as32 + 65536u;           // B: 2 x 64KB

    const int tid  = threadIdx.x;
    const int lane = tid & 31;
    const int w    = tid >> 5;
    const int wm   = w >> 2;          // 0..3 (32-row slab)
    const int wn   = w & 3;           // 0..3 (32-col slab)
    const int rowBase = blockIdx.x * 128;
    const int qBase   = blockIdx.y * QCHUNK;

    // ---- async load A (128x256 bf16) + B tile 0 ----
    #pragma unroll
    for (int i = 0; i < 8; ++i) {
        int c = i * 512 + tid;
        uint32_t row = (uint32_t)(c >> 5), k16 = (uint32_t)(c & 31);
        cp_async16(as32 + sw(row, k16 * 16),
                   (const char*)(g_ehi + (size_t)(rowBase + row) * DDIM) + k16 * 16);
    }
    #pragma unroll
    for (int i = 0; i < 8; ++i) {
        int c = i * 512 + tid;
        uint32_t row = (uint32_t)(c >> 5), k16 = (uint32_t)(c & 31);
        cp_async16(bs32 + sw(row, k16 * 16),
                   (const char*)(g_qhi + (size_t)(qBase + row) * DDIM) + k16 * 16);
    }
    CP_COMMIT();
    CP_WAIT0();
    __syncthreads();

    float tv[4][2];
    int   tix[4][2];
    #pragma unroll
    for (int s = 0; s < 4; ++s) {
        tv[s][0] = -INFINITY; tv[s][1] = -INFINITY;
        tix[s][0] = 0x7fffffff; tix[s][1] = 0x7fffffff;
    }

    for (int ct = 0; ct < NTILE; ++ct) {
        // prefetch next B tile
        if (ct + 1 < NTILE) {
            const uint32_t nbuf = bs32 + (uint32_t)((ct + 1) & 1) * 65536u;
            #pragma unroll
            for (int i = 0; i < 8; ++i) {
                int c = i * 512 + tid;
                uint32_t row = (uint32_t)(c >> 5), k16 = (uint32_t)(c & 31);
                cp_async16(nbuf + sw(row, k16 * 16),
                           (const char*)(g_qhi + (size_t)(qBase + (ct + 1) * 128 + row) * DDIM) + k16 * 16);
            }
            CP_COMMIT();
        }

        const uint32_t bbuf = bs32 + (uint32_t)(ct & 1) * 65536u;
        float acc[2][4][4];
        #pragma unroll
        for (int mi = 0; mi < 2; ++mi)
            #pragma unroll
            for (int ni = 0; ni < 4; ++ni)
                #pragma unroll
                for (int d = 0; d < 4; ++d) acc[mi][ni][d] = 0.0f;

        // fragment double-buffer across the 16 k-steps
        uint32_t a[2][2][4], b[2][4][2];
        load_a_frags(as32, 0, wm, lane, a[0]);
        load_b_frags(bbuf, 0, wn, lane, b[0]);

        #pragma unroll
        for (int kf = 0; kf < 16; ++kf) {
            const int cur = kf & 1;
            if (kf < 15) {
                load_a_frags(as32, kf + 1, wm, lane, a[cur ^ 1]);
                load_b_frags(bbuf, kf + 1, wn, lane, b[cur ^ 1]);
            }
            #pragma unroll
            for (int mi = 0; mi < 2; ++mi)
                #pragma unroll
                for (int ni = 0; ni < 4; ++ni)
                    mma16816(acc[mi][ni][0], acc[mi][ni][1], acc[mi][ni][2], acc[mi][ni][3],
                             a[cur][mi][0], a[cur][mi][1], a[cur][mi][2], a[cur][mi][3],
                             b[cur][ni][0], b[cur][ni][1]);
        }

        // epilogue: approx top-2 per owned row-slot
        const int colT = qBase + ct * 128 + wn * 32 + (lane & 3) * 2;
        #pragma unroll
        for (int mi = 0; mi < 2; ++mi)
            #pragma unroll
            for (int ni = 0; ni < 4; ++ni)
                #pragma unroll
                for (int d = 0; d < 4; ++d) {
                    float v = acc[mi][ni][d];
                    int   c = colT + ni * 8 + (d & 1);
                    int   s = mi * 2 + (d >> 1);
                    if (v > tv[s][0]) {
                        tv[s][1] = tv[s][0]; tix[s][1] = tix[s][0];
                        tv[s][0] = v;        tix[s][0] = c;
                    } else if (v > tv[s][1]) {
                        tv[s][1] = v;        tix[s][1] = c;
                    }
                }

        CP_WAIT0();
        __syncthreads();
    }

    // ---- CTA top-2 reduce (reuse A smem): 16 contributors x 2 per row ----
    float* sval = (float*)(smem + (as32 - sb));
    int*   sidx = (int*)(sval + 128 * 32);
    const int own = wn * 4 + (lane & 3);
    #pragma unroll
    for (int s = 0; s < 4; ++s) {
        int rowL = wm * 32 + (s >> 1) * 16 + (s & 1) * 8 + (lane >> 2);
        sval[rowL * 32 + own * 2 + 0] = tv[s][0];
        sval[rowL * 32 + own * 2 + 1] = tv[s][1];
        sidx[rowL * 32 + own * 2 + 0] = tix[s][0];
        sidx[rowL * 32 + own * 2 + 1] = tix[s][1];
    }
    __syncthreads();
    if (tid < 128) {
        float v1 = -INFINITY, v2 = -INFINITY;
        int   i1 = 0x7fffffff, i2 = 0x7fffffff;
        #pragma unroll
        for (int t = 0; t < 32; ++t) {
            float v = sval[tid * 32 + t];
            int   i = sidx[tid * 32 + t];
            if (v > v1) { v2 = v1; i2 = i1; v1 = v; i1 = i; }
            else if (v > v2) { v2 = v; i2 = i; }
        }
        size_t o = (size_t)(rowBase + tid) * (2 * QS) + blockIdx.y * 2;
        g_c2val[o + 0] = v1; g_c2idx[o + 0] = i1;
        g_c2val[o + 1] = v2; g_c2idx[o + 1] = i2;
    }
}

// ============================================================
// Kernel 2: exact fp32 rescore of 64 candidates -> g_gidx.
// ============================================================
__global__ void rescore_kernel(const float* __restrict__ emb,
                               const float* __restrict__ queue)
{
    int warp = (blockIdx.x * blockDim.x + threadIdx.x) >> 5;
    int lane = threadIdx.x & 31;
    if (warp >= B_TOT) return;

    size_t o = (size_t)warp * (2 * QS);
    float v0 = g_c2val[o + lane];
    float v1 = g_c2val[o + 32 + lane];
    int   i0 = g_c2idx[o + lane];
    int   i1 = g_c2idx[o + 32 + lane];

    float m = fmaxf(v0, v1);
    #pragma unroll
    for (int sh = 16; sh; sh >>= 1) m = fmaxf(m, __shfl_xor_sync(0xffffffffu, m, sh));
    const float thr = m - RESCORE_MARGIN;

    const float4* e4 = (const float4*)(emb + (size_t)warp * DDIM);
    float s0 = -INFINITY, s1 = -INFINITY;
    if (v0 >= thr) {
        const float4* q4 = (const float4*)(queue + (size_t)i0 * DDIM);
        float acc = 0.0f;
        #pragma unroll 8
        for (int k = 0; k < 64; ++k) {
            float4 a = e4[k], b = q4[k];
            acc = fmaf(a.x, b.x, acc); acc = fmaf(a.y, b.y, acc);
            acc = fmaf(a.z, b.z, acc); acc = fmaf(a.w, b.w, acc);
        }
        s0 = acc;
    }
    if (v1 >= thr) {
        const float4* q4 = (const float4*)(queue + (size_t)i1 * DDIM);
        float acc = 0.0f;
        #pragma unroll 8
        for (int k = 0; k < 64; ++k) {
            float4 a = e4[k], b = q4[k];
            acc = fmaf(a.x, b.x, acc); acc = fmaf(a.y, b.y, acc);
            acc = fmaf(a.z, b.z, acc); acc = fmaf(a.w, b.w, acc);
        }
        s1 = acc;
    }
    float bv = s0; int bi = i0;
    if (s1 > bv || (s1 == bv && i1 < bi)) { bv = s1; bi = i1; }
    #pragma unroll
    for (int sh = 16; sh; sh >>= 1) {
        float ov = __shfl_xor_sync(0xffffffffu, bv, sh);
        int   oi = __shfl_xor_sync(0xffffffffu, bi, sh);
        if (ov > bv || (ov == bv && oi < bi)) { bv = ov; bi = oi; }
    }
    if (lane == 0) g_gidx[warp] = bi;
}

// ============================================================
// Kernel 3: bf16 mma.sync logits GEMM + fp32 online logsumexp partials.
// grid (16 row-tiles, CS colgroups, 2 dirs); 256 thr, 8 warps (4x2), tile 32x64.
// ============================================================
__global__ __launch_bounds__(256, 1)
void logits_mma_kernel()
{
    extern __shared__ char smem[];
    const uint32_t sb   = smem_to_u32(smem);
    const uint32_t as32 = (sb + 1023u) & ~1023u;
    const uint32_t bs32 = as32 + 65536u;

    const int tid  = threadIdx.x;
    const int lane = tid & 31;
    const int w    = tid >> 5;
    const int wm   = w >> 1;
    const int wn   = w & 1;
    const int dir      = blockIdx.z;
    const int rowBase  = blockIdx.x * 128;
    const int colBase  = blockIdx.y * NCOL;
    const int predBase = (dir == 0) ? HALF : 0;
    const int idxBase  = dir * HALF;

    // ---- gather A rows (nn in bf16) + B tile 0 ----
    #pragma unroll
    for (int i = 0; i < 16; ++i) {
        int c = i * 256 + tid;
        uint32_t row = (uint32_t)(c >> 5), k16 = (uint32_t)(c & 31);
        int qi = g_gidx[idxBase + rowBase + (int)row];
        cp_async16(as32 + sw(row, k16 * 16),
                   (const char*)(g_qhi + (size_t)qi * DDIM) + k16 * 16);
    }
    #pragma unroll
    for (int i = 0; i < 16; ++i) {
        int c = i * 256 + tid;
        uint32_t row = (uint32_t)(c >> 5), k16 = (uint32_t)(c & 31);
        cp_async16(bs32 + sw(row, k16 * 16),
                   (const char*)(g_phi + (size_t)(predBase + colBase + row) * DDIM) + k16 * 16);
    }
    CP_COMMIT();
    CP_WAIT0();
    __syncthreads();

    float lm[4], ls[4];
    #pragma unroll
    for (int s = 0; s < 4; ++s) { lm[s] = -INFINITY; ls[s] = 0.0f; }

    for (int ct = 0; ct < NTILE_LOG; ++ct) {
        if (ct + 1 < NTILE_LOG) {
            const uint32_t nbuf = bs32 + (uint32_t)((ct + 1) & 1) * 65536u;
            #pragma unroll
            for (int i = 0; i < 16; ++i) {
                int c = i * 256 + tid;
                uint32_t row = (uint32_t)(c >> 5), k16 = (uint32_t)(c & 31);
                cp_async16(nbuf + sw(row, k16 * 16),
                           (const char*)(g_phi + (size_t)(predBase + colBase + (ct + 1) * 128 + row) * DDIM) + k16 * 16);
            }
            CP_COMMIT();
        }

        const uint32_t bbuf = bs32 + (uint32_t)(ct & 1) * 65536u;
        float acc[2][8][4];
        #pragma unroll
        for (int mi = 0; mi < 2; ++mi)
            #pragma unroll
            for (int ni = 0; ni < 8; ++ni)
                #pragma unroll
                for (int d = 0; d < 4; ++d) acc[mi][ni][d] = 0.0f;

        #pragma unroll
        for (int kf = 0; kf < 16; ++kf) {
            uint32_t a[2][4];
            #pragma unroll
            for (int mi = 0; mi < 2; ++mi) {
                uint32_t row = (uint32_t)(wm * 32 + mi * 16 + (lane & 15));
                uint32_t kb  = (uint32_t)(kf * 32 + (lane >> 4) * 16);
                ldsm_x4(a[mi][0], a[mi][1], a[mi][2], a[mi][3], as32 + sw(row, kb));
            }
            uint32_t b[8][2];
            #pragma unroll
            for (int np = 0; np < 4; ++np) {
                uint32_t col = (uint32_t)(wn * 64 + np * 16 + (lane & 7) + ((lane >> 4) & 1) * 8);
                uint32_t kb  = (uint32_t)(kf * 32 + ((lane >> 3) & 1) * 16);
                uint32_t r0, r1, r2, r3;
                ldsm_x4(r0, r1, r2, r3, bbuf + sw(col, kb));
                b[2 * np][0] = r0; b[2 * np][1] = r1;
                b[2 * np + 1][0] = r2; b[2 * np + 1][1] = r3;
            }
            #pragma unroll
            for (int mi = 0; mi < 2; ++mi)
                #pragma unroll
                for (int ni = 0; ni < 8; ++ni)
                    mma16816(acc[mi][ni][0], acc[mi][ni][1], acc[mi][ni][2], acc[mi][ni][3],
                             a[mi][0], a[mi][1], a[mi][2], a[mi][3], b[ni][0], b[ni][1]);
        }

        // epilogue: online logsumexp (fp32)
        #pragma unroll
        for (int mi = 0; mi < 2; ++mi)
            #pragma unroll
            for (int ni = 0; ni < 8; ++ni)
                #pragma unroll
                for (int d = 0; d < 4; ++d) {
                    float x = acc[mi][ni][d] * INV_T;
                    int   s = mi * 2 + (d >> 1);
                    if (x > lm[s]) {
                        ls[s] = ls[s] * expf(lm[s] - x) + 1.0f;
                        lm[s] = x;
                    } else {
                        ls[s] += expf(x - lm[s]);
                    }
                }

        CP_WAIT0();
        __syncthreads();
    }

    // ---- CTA LSE reduce: 8 contributors per row ----
    float* sM = (float*)(smem + (as32 - sb));
    float* sS = sM + 128 * 8;
    const int cont = wn * 4 + (lane & 3);
    #pragma unroll
    for (int s = 0; s < 4; ++s) {
        int rowL = wm * 32 + (s >> 1) * 16 + (s & 1) * 8 + (lane >> 2);
        sM[rowL * 8 + cont] = lm[s];
        sS[rowL * 8 + cont] = ls[s];
    }
    __syncthreads();
    if (tid < 128) {
        float M = -INFINITY;
        #pragma unroll
        for (int t = 0; t < 8; ++t) M = fmaxf(M, sM[tid * 8 + t]);
        float S = 0.0f;
        #pragma unroll
        for (int t = 0; t < 8; ++t) S += sS[tid * 8 + t] * expf(sM[tid * 8 + t] - M);
        int row = rowBase + tid;
        g_lsem[(size_t)(idxBase + row) * CS + blockIdx.y] = M;
        g_lses[(size_t)(idxBase + row) * CS + blockIdx.y] = S;
    }
}

// ============================================================
// Kernel 4: per-row loss = logsumexp - exact fp32 diagonal logit.
// ============================================================
__global__ void ce_finalize_kernel(const float* __restrict__ queue,
                                   const float* __restrict__ preds)
{
    int warp = (blockIdx.x * blockDim.x + threadIdx.x) >> 5;
    int lane = threadIdx.x & 31;
    #pragma unroll
    for (int rr = 0; rr < 4; ++rr) {
        int ridx = warp * 4 + rr;
        if (ridx >= 2 * HALF) return;
        int dir = ridx >> 11;
        int row = ridx & (HALF - 1);
        int qi  = g_gidx[dir * HALF + row];
        const float* a = queue + (size_t)qi * DDIM;
        const float* b = preds + (size_t)(((dir == 0) ? HALF : 0) + row) * DDIM;
        float p = 0.0f;
        for (int k = lane; k < DDIM; k += 32) p = fmaf(a[k], b[k], p);
        #pragma unroll
        for (int o = 16; o; o >>= 1) p += __shfl_xor_sync(0xffffffffu, p, o);
        if (lane == 0) {
            float M = -INFINITY;
            #pragma unroll
            for (int t = 0; t < CS; ++t) M = fmaxf(M, g_lsem[(size_t)ridx * CS + t]);
            float S = 0.0f;
            #pragma unroll
            for (int t = 0; t < CS; ++t)
                S += g_lses[(size_t)ridx * CS + t] * expf(g_lsem[(size_t)ridx * CS + t] - M);
            float lse = M + logf(S);
            g_rowloss[ridx] = lse - p * INV_T;
        }
    }
}

// ============================================================
// Kernel 5: final reduction -> scalar loss
// ============================================================
__global__ void final_sum_kernel(float* __restrict__ out)
{
    __shared__ float sm0[256], sm1[256];
    int tid = threadIdx.x;
    float s0 = 0.0f, s1 = 0.0f;
    for (int i = tid; i < HALF; i += 256) {
        s0 += g_rowloss[i];
        s1 += g_rowloss[HALF + i];
    }
    sm0[tid] = s0; sm1[tid] = s1;
    __syncthreads();
    for (int o = 128; o; o >>= 1) {
        if (tid < o) { sm0[tid] += sm0[tid + o]; sm1[tid] += sm1[tid + o]; }
        __syncthreads();
    }
    if (tid == 0)
        out[0] = 0.5f * (sm0[0] / (float)HALF + sm1[0] / (float)HALF);
}

// ============================================================
extern "C" void kernel_launch(void* const* d_in, const int* in_sizes, int n_in,
                              void* d_out, int out_size)
{
    const float* emb   = (const float*)d_in[0];
    const float* preds = (const float*)d_in[1];
    const float* queue = (const float*)d_in[2];
    float* out = (float*)d_out;

    __nv_bfloat16 *qhi, *ehi, *phi;
    cudaGetSymbolAddress((void**)&qhi, g_qhi);
    cudaGetSymbolAddress((void**)&ehi, g_ehi);
    cudaGetSymbolAddress((void**)&phi, g_phi);

    to_bf16_kernel<<<(QTOT * DDIM / 4 + 255) / 256, 256>>>(queue, qhi, QTOT * DDIM / 4);
    to_bf16_kernel<<<(B_TOT * DDIM / 4 + 255) / 256, 256>>>(emb,   ehi, B_TOT * DDIM / 4);
    to_bf16_kernel<<<(B_TOT * DDIM / 4 + 255) / 256, 256>>>(preds, phi, B_TOT * DDIM / 4);

    const size_t smemArg = 1024 + 65536 + 131072;
    cudaFuncSetAttribute(argmax_mma_kernel,
                         cudaFuncAttributeMaxDynamicSharedMemorySize, (int)smemArg);
    argmax_mma_kernel<<<dim3(B_TOT / 128, QS), 512, smemArg>>>();

    rescore_kernel<<<B_TOT / 8, 256>>>(emb, queue);

    cudaFuncSetAttribute(logits_mma_kernel,
                         cudaFuncAttributeMaxDynamicSharedMemorySize, (int)smemArg);
    logits_mma_kernel<<<dim3(HALF / 128, CS, 2), 256, smemArg>>>();

    ce_finalize_kernel<<<128, 256>>>(queue, preds);
    final_sum_kernel<<<1, 256>>>(out);
}